// round 5
// baseline (speedup 1.0000x reference)
#include <cuda_runtime.h>
#include <cuda_fp16.h>
#include <cstdint>
#include <math.h>

// ---------------------------------------------------------------------------
// SelfAttention, legacy HMMA path, fp32-accurate fp16 hi/lo split
// (A@B = Ahi@Bhi + Ahi@Blo + Alo@Bhi, fp32 accumulate).
// All operands pre-split to fp16 hi/lo planes; GEMM mainloop is pure
// cp.async (4-stage) + ldmatrix + mma.sync.
//   GEMM1: qkv16 = hidden16 @ W16        (M=8192,N=3072,K=1024)  B=[K,N]
//   GEMM2: scores = Q16 @ K16^T * 1/32   (M=2048,N=2048,K=1024)  B=[N,K]
//   softmax -> P16 planes
//   GEMM3: out = P16 @ V16               (M=2048,N=1024,K=2048)  B=[K,N]
// ---------------------------------------------------------------------------

#define BATCH 4
#define SEQ   2048
#define EMB   1024
#define BS    8192

__device__ __half g_hidh[(long)BS * EMB];
__device__ __half g_hidl[(long)BS * EMB];
__device__ __half g_wh[(long)EMB * 3 * EMB];
__device__ __half g_wl[(long)EMB * 3 * EMB];
__device__ __half g_qkvh[(long)BS * 3 * EMB];
__device__ __half g_qkvl[(long)BS * 3 * EMB];
__device__ float  g_scores[(long)BATCH * SEQ * SEQ];
__device__ __half g_ph[(long)BATCH * SEQ * SEQ];
__device__ __half g_pl[(long)BATCH * SEQ * SEQ];

// ---------------- helpers ----------------
__device__ __forceinline__ uint32_t smem_u32(const void* p) {
    uint32_t a;
    asm("{ .reg .u64 t; cvta.to.shared.u64 t, %1; cvt.u32.u64 %0, t; }"
        : "=r"(a) : "l"(p));
    return a;
}

__device__ __forceinline__ void cp16(uint32_t d, const void* s) {
    asm volatile("cp.async.cg.shared.global [%0], [%1], 16;" :: "r"(d), "l"(s));
}

#define LDSM_X4(r, a)                                                        \
    asm volatile("ldmatrix.sync.aligned.m8n8.x4.shared.b16 {%0,%1,%2,%3}, [%4];" \
                 : "=r"((r)[0]), "=r"((r)[1]), "=r"((r)[2]), "=r"((r)[3])    \
                 : "r"(a))

#define LDSM_X4_T(r0, r1, r2, r3, a)                                         \
    asm volatile("ldmatrix.sync.aligned.m8n8.x4.trans.shared.b16 {%0,%1,%2,%3}, [%4];" \
                 : "=r"(r0), "=r"(r1), "=r"(r2), "=r"(r3)                    \
                 : "r"(a))

__device__ __forceinline__ void mma16816(float* c, const uint32_t* a, const uint32_t* b) {
    asm volatile(
        "mma.sync.aligned.m16n8k16.row.col.f32.f16.f16.f32 "
        "{%0,%1,%2,%3}, {%4,%5,%6,%7}, {%8,%9}, {%0,%1,%2,%3};"
        : "+f"(c[0]), "+f"(c[1]), "+f"(c[2]), "+f"(c[3])
        : "r"(a[0]), "r"(a[1]), "r"(a[2]), "r"(a[3]), "r"(b[0]), "r"(b[1]));
}

// ---------------- GEMM ----------------
// BM=BN=128, BK=32 halves, 256 threads = 8 warps (2M x 4N), warp tile 64x32.
// BNK=0: B gmem is [K,N] row-major (trans-ldmatrix).
// BNK=1: B gmem is [N,K] row-major (non-trans ldmatrix, A-style layout).
// OUTH=0: fp32 C (alpha applied). OUTH=1: fp16 hi/lo plane outputs.
#define A_ROW_B 80
#define A_PLANE 10240               // 128 * 80
#define BT_ROW_B 272
#define BT_PLANE 8704               // 32 * 272

template <int BNK, int OUTH>
__global__ __launch_bounds__(256, 1)
void hmma_gemm(const __half* __restrict__ Ah, const __half* __restrict__ Al,
               int lda, long sA,
               const __half* __restrict__ Bh, const __half* __restrict__ Bl,
               int ldb, long sB,
               float* __restrict__ C, __half* __restrict__ Ch, __half* __restrict__ Cl,
               int ldc, long sC, int K, float alpha)
{
    constexpr int BPLANE = BNK ? A_PLANE : BT_PLANE;
    constexpr int STAGE  = 2 * A_PLANE + 2 * BPLANE;

    extern __shared__ char sm[];
    const uint32_t sbase = smem_u32(sm);

    const int tid = threadIdx.x;
    const int lane = tid & 31;
    const int wid = tid >> 5;

    const int bz = blockIdx.z;
    Ah += (long)bz * sA;  Al += (long)bz * sA;
    Bh += (long)bz * sB;  Bl += (long)bz * sB;
    const int row0 = blockIdx.y * 128;
    const int col0 = blockIdx.x * 128;

    const int mb = (wid >> 2) * 64;
    const int nb = (wid & 3) * 32;

    // loader indices
    const int aR = tid >> 1;                 // 0..127
    const int aK16 = (tid & 1) * 16;         // halves
    const int aOff = (tid & 1) * 32;         // bytes
    const int btK = tid >> 3;                // 0..31 (BNK=0)
    const int btN = (tid & 7) * 16;          // halves
    const int btOff = (tid & 7) * 32;        // bytes

    // fragment relative addresses
    const uint32_t aRel = (uint32_t)((mb + (lane & 15)) * A_ROW_B + (lane >> 4) * 16);
    const uint32_t bRel = BNK
        ? (uint32_t)((nb + (lane & 7) + ((lane >> 4) & 1) * 8) * A_ROW_B + ((lane >> 3) & 1) * 16)
        : (uint32_t)(((lane & 7) + ((lane >> 3) & 1) * 8) * BT_ROW_B + (nb + (lane >> 4) * 8) * 2);

    float acc[4][4][4];
    #pragma unroll
    for (int i = 0; i < 4; i++)
        #pragma unroll
        for (int j = 0; j < 4; j++)
            #pragma unroll
            for (int e = 0; e < 4; e++) acc[i][j][e] = 0.0f;

    const int nIter = K / 32;

    auto issue = [&](int kb) {
        const uint32_t st = sbase + (uint32_t)(kb & 3) * STAGE;
        const int k0 = kb * 32;
        // A hi/lo
        {
            const __half* sh = Ah + (long)(row0 + aR) * lda + k0 + aK16;
            const __half* sl = Al + (long)(row0 + aR) * lda + k0 + aK16;
            uint32_t d = st + (uint32_t)(aR * A_ROW_B + aOff);
            cp16(d, sh); cp16(d + 16, sh + 8);
            cp16(d + A_PLANE, sl); cp16(d + A_PLANE + 16, sl + 8);
        }
        // B hi/lo
        if (BNK) {
            const __half* sh = Bh + (long)(col0 + aR) * ldb + k0 + aK16;
            const __half* sl = Bl + (long)(col0 + aR) * ldb + k0 + aK16;
            uint32_t d = st + 2 * A_PLANE + (uint32_t)(aR * A_ROW_B + aOff);
            cp16(d, sh); cp16(d + 16, sh + 8);
            cp16(d + BPLANE, sl); cp16(d + BPLANE + 16, sl + 8);
        } else {
            const __half* sh = Bh + (long)(k0 + btK) * ldb + col0 + btN;
            const __half* sl = Bl + (long)(k0 + btK) * ldb + col0 + btN;
            uint32_t d = st + 2 * A_PLANE + (uint32_t)(btK * BT_ROW_B + btOff);
            cp16(d, sh); cp16(d + 16, sh + 8);
            cp16(d + BPLANE, sl); cp16(d + BPLANE + 16, sl + 8);
        }
    };

    // prologue: stages 0..2
    #pragma unroll
    for (int s = 0; s < 3; s++) {
        issue(s);
        asm volatile("cp.async.commit_group;" ::: "memory");
    }

    for (int kb = 0; kb < nIter; kb++) {
        asm volatile("cp.async.wait_group 2;" ::: "memory");
        __syncthreads();

        if (kb + 3 < nIter) issue(kb + 3);
        asm volatile("cp.async.commit_group;" ::: "memory");

        const uint32_t st = sbase + (uint32_t)(kb & 3) * STAGE;
        #pragma unroll
        for (int ks = 0; ks < 2; ks++) {
            uint32_t ah[4][4], al[4][4], bh[4][2], bl[4][2];
            #pragma unroll
            for (int i = 0; i < 4; i++) {
                uint32_t ad = st + aRel + (uint32_t)(i * 16 * A_ROW_B + ks * 32);
                LDSM_X4(ah[i], ad);
                LDSM_X4(al[i], ad + A_PLANE);
            }
            #pragma unroll
            for (int j2 = 0; j2 < 2; j2++) {
                uint32_t bd;
                if (BNK)
                    bd = st + 2 * A_PLANE + bRel + (uint32_t)(ks * 32 + j2 * 16 * A_ROW_B);
                else
                    bd = st + 2 * A_PLANE + bRel + (uint32_t)(ks * 16 * BT_ROW_B + j2 * 32);
                if (BNK) {
                    LDSM_X4(bh[2 * j2], bd);       // r0,r1 = n-oct0 (b0,b1); r2,r3 = n-oct1
                    LDSM_X4(bl[2 * j2], bd + BPLANE);
                } else {
                    LDSM_X4_T(bh[2 * j2][0], bh[2 * j2][1], bh[2 * j2 + 1][0], bh[2 * j2 + 1][1], bd);
                    LDSM_X4_T(bl[2 * j2][0], bl[2 * j2][1], bl[2 * j2 + 1][0], bl[2 * j2 + 1][1],
                              bd + BPLANE);
                }
            }
            // NOTE (BNK=1): LDSM_X4 wrote 4 regs into bh[2*j2][0..1] and bh[2*j2+1][0..1]
            // contiguously (arrays adjacent), giving the same pairing as the trans path.
            #pragma unroll
            for (int i = 0; i < 4; i++)
                #pragma unroll
                for (int j = 0; j < 4; j++) mma16816(acc[i][j], ah[i], bh[j]);
            #pragma unroll
            for (int i = 0; i < 4; i++)
                #pragma unroll
                for (int j = 0; j < 4; j++) mma16816(acc[i][j], ah[i], bl[j]);
            #pragma unroll
            for (int i = 0; i < 4; i++)
                #pragma unroll
                for (int j = 0; j < 4; j++) mma16816(acc[i][j], al[i], bh[j]);
        }
        __syncthreads();
    }

    // epilogue
    #pragma unroll
    for (int i = 0; i < 4; i++) {
        const int r = row0 + mb + i * 16 + (lane >> 2);
        #pragma unroll
        for (int j = 0; j < 4; j++) {
            const int c = col0 + nb + j * 8 + (lane & 3) * 2;
            float v0 = acc[i][j][0] * alpha, v1 = acc[i][j][1] * alpha;
            float v2 = acc[i][j][2] * alpha, v3 = acc[i][j][3] * alpha;
            if (OUTH) {
                __half h0 = __float2half_rn(v0), h1 = __float2half_rn(v1);
                __half h2 = __float2half_rn(v2), h3 = __float2half_rn(v3);
                __half l0 = __float2half_rn(v0 - __half2float(h0));
                __half l1 = __float2half_rn(v1 - __half2float(h1));
                __half l2 = __float2half_rn(v2 - __half2float(h2));
                __half l3 = __float2half_rn(v3 - __half2float(h3));
                long o0 = (long)(r + (long)bz * (sC)) * 0;  // (silence unused warn path)
                (void)o0;
                __half* chp = Ch + (long)bz * sC;
                __half* clp = Cl + (long)bz * sC;
                *reinterpret_cast<__half2*>(chp + (long)r * ldc + c) = __halves2half2(h0, h1);
                *reinterpret_cast<__half2*>(chp + (long)(r + 8) * ldc + c) = __halves2half2(h2, h3);
                *reinterpret_cast<__half2*>(clp + (long)r * ldc + c) = __halves2half2(l0, l1);
                *reinterpret_cast<__half2*>(clp + (long)(r + 8) * ldc + c) = __halves2half2(l2, l3);
            } else {
                float* cp = C + (long)bz * sC;
                *reinterpret_cast<float2*>(cp + (long)r * ldc + c) = make_float2(v0, v1);
                *reinterpret_cast<float2*>(cp + (long)(r + 8) * ldc + c) = make_float2(v2, v3);
            }
        }
    }
}

// ---------------- fp32 -> fp16 hi/lo split convert ----------------
__global__ __launch_bounds__(256)
void cvt_split(const float4* __restrict__ src, __half2* __restrict__ dh,
               __half2* __restrict__ dl, long n4)
{
    long i = blockIdx.x * 256L + threadIdx.x;
    long stride = (long)gridDim.x * 256;
    for (; i < n4; i += stride) {
        float4 v = src[i];
        __half h0 = __float2half_rn(v.x), h1 = __float2half_rn(v.y);
        __half h2 = __float2half_rn(v.z), h3 = __float2half_rn(v.w);
        dh[2 * i]     = __halves2half2(h0, h1);
        dh[2 * i + 1] = __halves2half2(h2, h3);
        dl[2 * i]     = __halves2half2(__float2half_rn(v.x - __half2float(h0)),
                                       __float2half_rn(v.y - __half2float(h1)));
        dl[2 * i + 1] = __halves2half2(__float2half_rn(v.z - __half2float(h2)),
                                       __float2half_rn(v.w - __half2float(h3)));
    }
}

// ---------------- softmax: fp32 scores row -> fp16 hi/lo P planes ----------
__global__ __launch_bounds__(256)
void softmax_kernel(const float* __restrict__ scores,
                    __half2* __restrict__ ph, __half2* __restrict__ pl)
{
    __shared__ float red[8];
    const long row = blockIdx.x;
    const float4* r4 = reinterpret_cast<const float4*>(scores + row * (long)SEQ);
    const int tid = threadIdx.x;
    const int wid = tid >> 5, lane = tid & 31;

    float4 a = r4[tid];
    float4 b = r4[tid + 256];

    float m = fmaxf(fmaxf(fmaxf(a.x, a.y), fmaxf(a.z, a.w)),
                    fmaxf(fmaxf(b.x, b.y), fmaxf(b.z, b.w)));
    #pragma unroll
    for (int o = 16; o; o >>= 1) m = fmaxf(m, __shfl_xor_sync(0xffffffffu, m, o));
    if (lane == 0) red[wid] = m;
    __syncthreads();
    float rowmax = red[0];
    #pragma unroll
    for (int i = 1; i < 8; i++) rowmax = fmaxf(rowmax, red[i]);
    __syncthreads();

    a.x = __expf(a.x - rowmax); a.y = __expf(a.y - rowmax);
    a.z = __expf(a.z - rowmax); a.w = __expf(a.w - rowmax);
    b.x = __expf(b.x - rowmax); b.y = __expf(b.y - rowmax);
    b.z = __expf(b.z - rowmax); b.w = __expf(b.w - rowmax);

    float s = a.x + a.y + a.z + a.w + b.x + b.y + b.z + b.w;
    #pragma unroll
    for (int o = 16; o; o >>= 1) s += __shfl_xor_sync(0xffffffffu, s, o);
    if (lane == 0) red[wid] = s;
    __syncthreads();
    float tot = red[0];
    #pragma unroll
    for (int i = 1; i < 8; i++) tot += red[i];
    const float inv = 1.0f / tot;

    a.x *= inv; a.y *= inv; a.z *= inv; a.w *= inv;
    b.x *= inv; b.y *= inv; b.z *= inv; b.w *= inv;

    __half2* phr = ph + row * (SEQ / 2);
    __half2* plr = pl + row * (SEQ / 2);
    auto emit = [&](int idx2, float x, float y) {
        __half hx = __float2half_rn(x), hy = __float2half_rn(y);
        phr[idx2] = __halves2half2(hx, hy);
        plr[idx2] = __halves2half2(__float2half_rn(x - __half2float(hx)),
                                   __float2half_rn(y - __half2float(hy)));
    };
    emit(2 * tid, a.x, a.y);
    emit(2 * tid + 1, a.z, a.w);
    emit(2 * (tid + 256), b.x, b.y);
    emit(2 * (tid + 256) + 1, b.z, b.w);
}

// ---------------- launch ----------------
extern "C" void kernel_launch(void* const* d_in, const int* in_sizes, int n_in,
                              void* d_out, int out_size)
{
    const float* hidden = (const float*)d_in[0];
    const float* W      = (const float*)d_in[1];
    float* out          = (float*)d_out;

    __half *hidh, *hidl, *wh, *wl, *qkvh, *qkvl, *ph, *pl;
    float *scores;
    cudaGetSymbolAddress((void**)&hidh, g_hidh);
    cudaGetSymbolAddress((void**)&hidl, g_hidl);
    cudaGetSymbolAddress((void**)&wh, g_wh);
    cudaGetSymbolAddress((void**)&wl, g_wl);
    cudaGetSymbolAddress((void**)&qkvh, g_qkvh);
    cudaGetSymbolAddress((void**)&qkvl, g_qkvl);
    cudaGetSymbolAddress((void**)&scores, g_scores);
    cudaGetSymbolAddress((void**)&ph, g_ph);
    cudaGetSymbolAddress((void**)&pl, g_pl);

    constexpr int SMEM_BT = 4 * (2 * A_PLANE + 2 * BT_PLANE);  // 151552
    constexpr int SMEM_BN = 4 * (4 * A_PLANE);                 // 163840
    cudaFuncSetAttribute(hmma_gemm<0, 1>, cudaFuncAttributeMaxDynamicSharedMemorySize, SMEM_BT);
    cudaFuncSetAttribute(hmma_gemm<1, 0>, cudaFuncAttributeMaxDynamicSharedMemorySize, SMEM_BN);
    cudaFuncSetAttribute(hmma_gemm<0, 0>, cudaFuncAttributeMaxDynamicSharedMemorySize, SMEM_BT);

    // split inputs
    cvt_split<<<1024, 256>>>((const float4*)hidden, (__half2*)hidh, (__half2*)hidl,
                             (long)BS * EMB / 4);
    cvt_split<<<1024, 256>>>((const float4*)W, (__half2*)wh, (__half2*)wl,
                             (long)EMB * 3 * EMB / 4);

    // GEMM1: qkv16 = hidden16 @ W16   (B=[K,N], out=halves)
    hmma_gemm<0, 1><<<dim3(3 * EMB / 128, BS / 128, 1), 256, SMEM_BT>>>(
        hidh, hidl, EMB, 0,
        wh, wl, 3 * EMB, 0,
        nullptr, qkvh, qkvl, 3 * EMB, 0,
        EMB, 1.0f);

    // GEMM2: scores = Q16 @ K16^T * 1/32   (B=[N,K] = K-section rows)
    hmma_gemm<1, 0><<<dim3(SEQ / 128, SEQ / 128, BATCH), 256, SMEM_BN>>>(
        qkvh, qkvl, 3 * EMB, (long)SEQ * 3 * EMB,
        qkvh + EMB, qkvl + EMB, 3 * EMB, (long)SEQ * 3 * EMB,
        scores, nullptr, nullptr, SEQ, (long)SEQ * SEQ,
        EMB, 1.0f / 32.0f);

    // softmax -> P16 planes
    softmax_kernel<<<BATCH * SEQ, 256>>>(scores, (__half2*)ph, (__half2*)pl);

    // GEMM3: out = P16 @ V16   (B=[K,N] = V rows)
    hmma_gemm<0, 0><<<dim3(EMB / 128, SEQ / 128, BATCH), 256, SMEM_BT>>>(
        ph, pl, SEQ, (long)SEQ * SEQ,
        qkvh + 2 * EMB, qkvl + 2 * EMB, 3 * EMB, (long)SEQ * 3 * EMB,
        out, nullptr, nullptr, EMB, (long)SEQ * EMB,
        SEQ, 1.0f);
}